// round 6
// baseline (speedup 1.0000x reference)
#include <cuda_runtime.h>
#include <math.h>

// ---------------------------------------------------------------------------
// FractalDecoderV6 — fused single kernel, fp32, f32x2-packed FMA.
// R3 fix: GEMM2 contracts full K=512 (32 tiles), prefetch schedule updated.
// ---------------------------------------------------------------------------

#define Bn     16384
#define Ln     8
#define En     8
#define Sn     16384
#define Kn     32
#define HID    256
#define FFd    512
#define Tn     48
#define LATn   32
#define VOCAB  256
#define IN_DIM 161
#define FST    168

#define MROWS  32
#define NTHR   256
#define KT     16

typedef unsigned long long u64;

__device__ __forceinline__ void fma2(u64 &d, u64 a, u64 b) {
    asm volatile("fma.rn.f32x2 %0, %1, %2, %0;" : "+l"(d) : "l"(a), "l"(b));
}
__device__ __forceinline__ u64 pack2(float x, float y) {
    u64 r; asm("mov.b64 %0, {%1, %2};" : "=l"(r) : "f"(x), "f"(y)); return r;
}
__device__ __forceinline__ float2 unpack2(u64 v) {
    float2 f; asm("mov.b64 {%0, %1}, %2;" : "=f"(f.x), "=f"(f.y) : "l"(v)); return f;
}
__device__ __forceinline__ void cp16(float* sdst, const float* gsrc) {
    unsigned s = (unsigned)__cvta_generic_to_shared(sdst);
    asm volatile("cp.async.cg.shared.global [%0], [%1], 16;" :: "r"(s), "l"(gsrc));
}
__device__ __forceinline__ void cp_commit() { asm volatile("cp.async.commit_group;"); }
__device__ __forceinline__ void cp_wait1()  { asm volatile("cp.async.wait_group 1;"); }
__device__ __forceinline__ void cp_wait0()  { asm volatile("cp.async.wait_group 0;"); }

__device__ __forceinline__ float gelu_exact(float v) {
    return 0.5f * v * (1.0f + erff(v * 0.70710678118654752f));
}
__device__ __forceinline__ float tanh_acc(float x) {   // fast-math-proof tanh
    float a  = fabsf(x);
    float em = expm1f(-2.0f * a);
    float t  = -em / (2.0f + em);
    return copysignf(t, x);
}

__global__ void __launch_bounds__(NTHR, 1)
fractal_kernel(const float* __restrict__ x,   const float* __restrict__ z,
               const float* __restrict__ tbl,
               const float* __restrict__ W1,  const float* __restrict__ b1,
               const float* __restrict__ W2,  const float* __restrict__ b2,
               const float* __restrict__ Wf1, const float* __restrict__ bf1,
               const float* __restrict__ Wf2, const float* __restrict__ bf2,
               const float* __restrict__ Wo,  const float* __restrict__ bo,
               const int*   __restrict__ resolutions,
               const float* __restrict__ freqs,
               float* __restrict__ out)
{
    extern __shared__ float sm[];
    float* hs2 = sm;            // 32*256*2 floats (h duplicated pairs)
    float* gs  = sm + 16384;    // 32*512 floats   (g / feats)
    float* wb  = sm + 32768;    // 2 * 8192 floats (weight double buffer)

    const int t     = threadIdx.x;
    const int r0    = blockIdx.x * MROWS;
    const int rg    = t >> 6;
    const int rbase = rg * 8;
    const int ct    = t & 63;

    // ---------------- feature stage (feats alias gs, stride FST) ----------------
    {
        int   row = t >> 3;
        int   sub = t & 7;
        int   gr  = r0 + row;
        float xn  = fminf(fmaxf(x[gr], 0.0f), 1.0f);
        float* f  = gs + row * FST;
        if (sub == 0) f[0] = xn;
        float a = 6.2831855f * xn;
        #pragma unroll
        for (int q = 0; q < 4; q++) {
            int fi = sub * 4 + q;
            float arg = a * freqs[fi];
            double s, c;
            sincos((double)arg, &s, &c);
            f[1 + fi]      = (float)s;
            f[1 + Kn + fi] = (float)c;
        }
        {
            int   R  = resolutions[sub];
            float tf = xn * (float)(R - 1);
            int   i0 = (int)floorf(tf);
            int   i1 = min(i0 + 1, R - 1);
            float w  = tf - (float)i0;
            unsigned lt = (unsigned)(sub * 19349663);
            int h0 = (int)((((unsigned)i0 * 73856093u) ^ lt) & 16383u);
            int h1 = (int)((((unsigned)i1 * 73856093u) ^ lt) & 16383u);
            const float* e0 = tbl + ((size_t)sub * Sn + h0) * En;
            const float* e1 = tbl + ((size_t)sub * Sn + h1) * En;
            #pragma unroll
            for (int e = 0; e < En; e++)
                f[1 + 2 * Kn + sub * En + e] = e0[e] * (1.0f - w) + e1[e] * w;
        }
        #pragma unroll
        for (int q = 0; q < 4; q++)
            f[1 + 2 * Kn + Ln * En + sub * 4 + q] = z[(size_t)gr * LATn + sub * 4 + q];
    }
    __syncthreads();

    // ---------------- bias registers ----------------
    float2 bf1r[4], bf2r[2], b1r[2], b2r[2], bor[2];
    #pragma unroll
    for (int j = 0; j < 4; j++) bf1r[j] = *(const float2*)&bf1[2 * ct + 128 * j];
    #pragma unroll
    for (int j = 0; j < 2; j++) {
        bf2r[j] = *(const float2*)&bf2[2 * ct + 128 * j];
        b1r[j]  = *(const float2*)&b1 [2 * ct + 128 * j];
        b2r[j]  = *(const float2*)&b2 [2 * ct + 128 * j];
        bor[j]  = *(const float2*)&bo [2 * ct + 128 * j];
    }

    // ---------------- GEMM0: h1 = gelu(feats @ W1 + b1) ----------------
    {
        u64 acc[8][2];
        #pragma unroll
        for (int r = 0; r < 8; r++) { acc[r][0] = 0ull; acc[r][1] = 0ull; }
        for (int k = 0; k < IN_DIM; k++) {
            u64 wA = *(const u64*)&W1[k * HID + 2 * ct];
            u64 wB = *(const u64*)&W1[k * HID + 128 + 2 * ct];
            #pragma unroll
            for (int r = 0; r < 8; r++) {
                float hv = gs[(rbase + r) * FST + k];
                u64 hp = pack2(hv, hv);
                fma2(acc[r][0], hp, wA);
                fma2(acc[r][1], hp, wB);
            }
        }
        __syncthreads();
        #pragma unroll
        for (int r = 0; r < 8; r++)
            #pragma unroll
            for (int j = 0; j < 2; j++) {
                float2 v = unpack2(acc[r][j]);
                float g0 = gelu_exact(v.x + b1r[j].x);
                float g1 = gelu_exact(v.y + b1r[j].y);
                *(float4*)&hs2[((rbase + r) * HID + 2 * ct + 128 * j) * 2] =
                    make_float4(g0, g0, g1, g1);
            }
    }
    __syncthreads();

    float2 hreg[8][2];   // fp32 carried state (this thread's rows/cols)

    // ---------------- h = gelu(h1 @ W2 + b2) ----------------
    {
        u64 acc[8][2];
        #pragma unroll
        for (int r = 0; r < 8; r++) { acc[r][0] = 0ull; acc[r][1] = 0ull; }
        for (int k = 0; k < HID; k++) {
            u64 wA = *(const u64*)&W2[k * HID + 2 * ct];
            u64 wB = *(const u64*)&W2[k * HID + 128 + 2 * ct];
            #pragma unroll
            for (int r = 0; r < 8; r++) {
                float hv = hs2[((rbase + r) * HID + k) * 2];
                u64 hp = pack2(hv, hv);
                fma2(acc[r][0], hp, wA);
                fma2(acc[r][1], hp, wB);
            }
        }
        float4 res[8][2];
        #pragma unroll
        for (int r = 0; r < 8; r++)
            #pragma unroll
            for (int j = 0; j < 2; j++) {
                float2 v = unpack2(acc[r][j]);
                float h0 = gelu_exact(v.x + b2r[j].x);
                float h1 = gelu_exact(v.y + b2r[j].y);
                hreg[r][j] = make_float2(h0, h1);
                res[r][j]  = make_float4(h0, h0, h1, h1);
            }
        __syncthreads();
        #pragma unroll
        for (int r = 0; r < 8; r++)
            #pragma unroll
            for (int j = 0; j < 2; j++)
                *(float4*)&hs2[((rbase + r) * HID + 2 * ct + 128 * j) * 2] = res[r][j];
    }
    __syncthreads();

    // prime pipeline: Wf1 tile 0 -> buf 0
    for (int c = t; c < (KT * FFd) >> 2; c += NTHR) cp16(wb + c * 4, Wf1 + c * 4);
    cp_commit();

    // ---------------- 48-step scan ----------------
    #pragma unroll 1
    for (int step = 0; step < Tn; step++) {
        // ---- GEMM1: g = gelu(h @ Wf1 + bf1), K = 256 -> 16 tiles ----
        u64 acc1[8][4];
        #pragma unroll
        for (int r = 0; r < 8; r++)
            #pragma unroll
            for (int j = 0; j < 4; j++) acc1[r][j] = 0ull;

        #pragma unroll 1
        for (int kt = 0; kt < 16; kt++) {
            const float* src; int nf;
            if (kt < 15) { src = Wf1 + (kt + 1) * KT * FFd; nf = KT * FFd; }
            else         { src = Wf2;                       nf = KT * HID; }  // Wf2 tile0
            float* dst = wb + ((kt + 1) & 1) * 8192;
            for (int c = t; c < (nf >> 2); c += NTHR) cp16(dst + c * 4, src + c * 4);
            cp_commit();
            cp_wait1();
            __syncthreads();

            const float* wp = wb + (kt & 1) * 8192;
            const int k0 = kt * KT;
            #pragma unroll
            for (int kk = 0; kk < KT; kk++) {
                u64 w[4];
                #pragma unroll
                for (int j = 0; j < 4; j++)
                    w[j] = *(const u64*)&wp[kk * FFd + 2 * ct + 128 * j];
                #pragma unroll
                for (int r = 0; r < 8; r++) {
                    u64 hp = *(const u64*)&hs2[((rbase + r) * HID + k0 + kk) * 2];
                    fma2(acc1[r][0], hp, w[0]);
                    fma2(acc1[r][1], hp, w[1]);
                    fma2(acc1[r][2], hp, w[2]);
                    fma2(acc1[r][3], hp, w[3]);
                }
            }
            __syncthreads();
        }
        #pragma unroll
        for (int r = 0; r < 8; r++)
            #pragma unroll
            for (int j = 0; j < 4; j++) {
                float2 v = unpack2(acc1[r][j]);
                float g0 = gelu_exact(v.x + bf1r[j].x);
                float g1 = gelu_exact(v.y + bf1r[j].y);
                *(float2*)&gs[(rbase + r) * FFd + 2 * ct + 128 * j] = make_float2(g0, g1);
            }
        __syncthreads();

        // ---- GEMM2: u = tanh(g @ Wf2 + bf2), K = 512 -> 32 tiles (R3 FIX) ----
        u64 acc2[8][2];
        #pragma unroll
        for (int r = 0; r < 8; r++) { acc2[r][0] = 0ull; acc2[r][1] = 0ull; }

        #pragma unroll 1
        for (int kt = 0; kt < 32; kt++) {
            const float* src; int nf;
            if (kt < 31) { src = Wf2 + (kt + 1) * KT * HID; nf = KT * HID; }
            else         { src = Wf1;                       nf = KT * FFd; }  // next step tile0
            float* dst = wb + ((kt + 1) & 1) * 8192;
            for (int c = t; c < (nf >> 2); c += NTHR) cp16(dst + c * 4, src + c * 4);
            cp_commit();
            cp_wait1();
            __syncthreads();

            const float* wp = wb + (kt & 1) * 8192;
            const int k0 = kt * KT;
            #pragma unroll
            for (int kk2 = 0; kk2 < KT / 2; kk2++) {
                u64 wA[2], wB[2];
                #pragma unroll
                for (int j = 0; j < 2; j++) {
                    wA[j] = *(const u64*)&wp[(2 * kk2)     * HID + 2 * ct + 128 * j];
                    wB[j] = *(const u64*)&wp[(2 * kk2 + 1) * HID + 2 * ct + 128 * j];
                }
                #pragma unroll
                for (int r = 0; r < 8; r++) {
                    float2 h2 = *(const float2*)&gs[(rbase + r) * FFd + k0 + 2 * kk2];
                    u64 hA = pack2(h2.x, h2.x);
                    u64 hB = pack2(h2.y, h2.y);
                    fma2(acc2[r][0], hA, wA[0]);
                    fma2(acc2[r][1], hA, wA[1]);
                    fma2(acc2[r][0], hB, wB[0]);
                    fma2(acc2[r][1], hB, wB[1]);
                }
            }
            __syncthreads();
        }
        float4 newv[8][2];
        #pragma unroll
        for (int r = 0; r < 8; r++)
            #pragma unroll
            for (int j = 0; j < 2; j++) {
                float2 v = unpack2(acc2[r][j]);
                float u0 = tanh_acc(v.x + bf2r[j].x);
                float u1 = tanh_acc(v.y + bf2r[j].y);
                float h0 = 0.5f * hreg[r][j].x + 0.5f * u0;
                float h1 = 0.5f * hreg[r][j].y + 0.5f * u1;
                hreg[r][j] = make_float2(h0, h1);
                newv[r][j] = make_float4(h0, h0, h1, h1);
            }
        __syncthreads();
        #pragma unroll
        for (int r = 0; r < 8; r++)
            #pragma unroll
            for (int j = 0; j < 2; j++)
                *(float4*)&hs2[((rbase + r) * HID + 2 * ct + 128 * j) * 2] = newv[r][j];
        __syncthreads();
    }
    cp_wait0();

    // ---------------- final: out = h @ Wo + bo ----------------
    {
        u64 acc[8][2];
        #pragma unroll
        for (int r = 0; r < 8; r++) { acc[r][0] = 0ull; acc[r][1] = 0ull; }
        for (int k = 0; k < HID; k++) {
            u64 wA = *(const u64*)&Wo[k * VOCAB + 2 * ct];
            u64 wB = *(const u64*)&Wo[k * VOCAB + 128 + 2 * ct];
            #pragma unroll
            for (int r = 0; r < 8; r++) {
                float hv = hs2[((rbase + r) * HID + k) * 2];
                u64 hp = pack2(hv, hv);
                fma2(acc[r][0], hp, wA);
                fma2(acc[r][1], hp, wB);
            }
        }
        #pragma unroll
        for (int r = 0; r < 8; r++)
            #pragma unroll
            for (int j = 0; j < 2; j++) {
                float2 v = unpack2(acc[r][j]);
                v.x += bor[j].x;
                v.y += bor[j].y;
                *(float2*)&out[(size_t)(r0 + rbase + r) * VOCAB + 2 * ct + 128 * j] = v;
            }
    }
}

extern "C" void kernel_launch(void* const* d_in, const int* in_sizes, int n_in,
                              void* d_out, int out_size)
{
    (void)out_size;
    // Size-keyed input resolution (robust to metadata ordering conventions
    // that preserve relative order of equal-sized inputs).
    const float *x=0, *z=0, *tbl=0, *W1=0, *b1=0, *W2=0, *b2=0,
                *Wf1=0, *bf1=0, *Wf2=0, *bf2=0, *Wo=0, *bo=0, *frq=0;
    const int* res = 0;
    int c65536 = 0, c131072 = 0, c256 = 0;
    for (int i = 0; i < n_in; i++) {
        const void* p = d_in[i];
        switch (in_sizes[i]) {
            case 16384:   x   = (const float*)p; break;
            case 524288:  z   = (const float*)p; break;
            case 1048576: tbl = (const float*)p; break;
            case 41216:   W1  = (const float*)p; break;
            case 512:     bf1 = (const float*)p; break;
            case 8:       res = (const int*)p;   break;
            case 32:      frq = (const float*)p; break;
            case 65536:   if (c65536++  == 0) W2  = (const float*)p; else Wo  = (const float*)p; break;
            case 131072:  if (c131072++ == 0) Wf1 = (const float*)p; else Wf2 = (const float*)p; break;
            case 256:
                switch (c256++) {
                    case 0: b1  = (const float*)p; break;
                    case 1: b2  = (const float*)p; break;
                    case 2: bf2 = (const float*)p; break;
                    default: bo = (const float*)p; break;
                }
                break;
            default: break;
        }
    }
    float* out = (float*)d_out;

    const int smem = 48 * 1024 * 4;   // 196608 bytes
    cudaFuncSetAttribute(fractal_kernel, cudaFuncAttributeMaxDynamicSharedMemorySize, smem);
    fractal_kernel<<<Bn / MROWS, NTHR, smem>>>(x, z, tbl, W1, b1, W2, b2,
                                               Wf1, bf1, Wf2, bf2, Wo, bo,
                                               res, frq, out);
}

// round 9
// speedup vs baseline: 3.2317x; 3.2317x over previous
#include <cuda_runtime.h>
#include <math.h>

// ---------------------------------------------------------------------------
// FractalDecoderV6 — warp-level tf32 mma.sync rewrite (compute_100-safe).
// 128 rows/CTA, 128 CTAs, 512 threads. Weights pre-packed to B-fragment tape.
// R8: fix EPI256 macro (variadic) — no functional changes vs R7 design.
// ---------------------------------------------------------------------------

typedef unsigned int u32;

#define Bn    16384
#define Tn    48
#define MROWS 128
#define NTHR  512

#define HSTR 256     // h row stride (floats), XOR-swizzled
#define GSTR 128     // g slice row stride
#define FSTR 224     // feats row stride

#define H_OFF  0
#define G_OFF  131072
#define WB_OFF 196608
#define SMEM_BYTES 229376

// tape segment offsets (floats)
#define OFF_W1  0
#define OFF_W2  45056
#define OFF_WF1 110592
#define OFF_WF2 241664
#define OFF_WO  372736
#define NTAPE   438272
__device__ float g_tape[NTAPE];

static __device__ __forceinline__ u32 s2u(const void* p){
    u32 a; asm("{ .reg .u64 t; cvta.to.shared.u64 t, %1; cvt.u32.u64 %0, t; }":"=r"(a):"l"(p)); return a;
}
static __device__ __forceinline__ void cp16u(u32 dst, const float* src){
    asm volatile("cp.async.cg.shared.global [%0], [%1], 16;" :: "r"(dst), "l"(src));
}
static __device__ __forceinline__ void cp_commit(){ asm volatile("cp.async.commit_group;"); }
static __device__ __forceinline__ void cp_wait1(){ asm volatile("cp.async.wait_group 1;"); }
static __device__ __forceinline__ void cp_wait0(){ asm volatile("cp.async.wait_group 0;"); }
static __device__ __forceinline__ u32 cvtf(float f){
    u32 u; asm("cvt.rna.tf32.f32 %0, %1;" : "=r"(u) : "f"(f)); return u;
}
static __device__ __forceinline__ float lds1(u32 a){
    float v; asm volatile("ld.shared.b32 %0, [%1];" : "=f"(v) : "r"(a)); return v;
}
static __device__ __forceinline__ void lds2u(u32 a, u32 &x, u32 &y){
    asm volatile("ld.shared.v2.b32 {%0,%1}, [%2];" : "=r"(x), "=r"(y) : "r"(a));
}
static __device__ __forceinline__ void lds2f(u32 a, float &x, float &y){
    asm volatile("ld.shared.v2.b32 {%0,%1}, [%2];" : "=f"(x), "=f"(y) : "r"(a));
}
static __device__ __forceinline__ void sts1(u32 a, float v){
    asm volatile("st.shared.b32 [%0], %1;" :: "r"(a), "f"(v) : "memory");
}
static __device__ __forceinline__ void sts2(u32 a, float x, float y){
    asm volatile("st.shared.v2.b32 [%0], {%1,%2};" :: "r"(a), "f"(x), "f"(y) : "memory");
}
#define MMA(d, a, b0v, b1v) \
    asm volatile("mma.sync.aligned.m16n8k8.row.col.f32.tf32.tf32.f32 " \
        "{%0,%1,%2,%3}, {%4,%5,%6,%7}, {%8,%9}, {%0,%1,%2,%3};" \
        : "+f"((d)[0]),"+f"((d)[1]),"+f"((d)[2]),"+f"((d)[3]) \
        : "r"((a)[0]),"r"((a)[1]),"r"((a)[2]),"r"((a)[3]), "r"(b0v), "r"(b1v))

static __device__ __forceinline__ float gelu_e(float v){
    return 0.5f*v*(1.0f+erff(v*0.70710678118654752f));
}
static __device__ __forceinline__ float tanh_a(float x){
    float a = fabsf(x), em = expm1f(-2.0f*a);
    return copysignf(-em/(2.0f+em), x);
}

// --------- prep: tf32-round weights + pack into B-fragment tape ---------
// Per (kc, ntile): 64 floats = [lane 0..31][j 0..1];
//   value(lane, j) = W[kc*8 + (lane&3) + 4*j , ntile*8 + (lane>>2)]
__global__ void prep_tape(const float* __restrict__ W1, const float* __restrict__ W2,
                          const float* __restrict__ Wf1, const float* __restrict__ Wf2,
                          const float* __restrict__ Wo){
    int e = blockIdx.x*blockDim.x + threadIdx.x;
    if (e >= NTAPE) return;
    int lane, j, kc, nt, k, n;
    float v;
    if (e < OFF_W2){
        int q = e; kc = q>>11; int r2 = q&2047; nt = r2>>6; int li = r2&63; lane = li>>1; j = li&1;
        k = kc*8 + (lane&3) + 4*j; n = nt*8 + (lane>>2);
        v = (k < 161) ? W1[k*256 + n] : 0.0f;
    } else if (e < OFF_WF1){
        int q = e-OFF_W2; kc = q>>11; int r2 = q&2047; nt = r2>>6; int li = r2&63; lane = li>>1; j = li&1;
        k = kc*8 + (lane&3) + 4*j; n = nt*8 + (lane>>2);
        v = W2[k*256 + n];
    } else if (e < OFF_WF2){
        int q = e-OFF_WF1; int s = q>>15; int q2 = q&32767;
        kc = q2>>10; int r2 = q2&1023; nt = r2>>6; int li = r2&63; lane = li>>1; j = li&1;
        k = kc*8 + (lane&3) + 4*j; n = s*128 + nt*8 + (lane>>2);
        v = Wf1[k*512 + n];
    } else if (e < OFF_WO){
        int q = e-OFF_WF2; int s = q>>15; int q2 = q&32767;
        kc = q2>>11; int r2 = q2&2047; nt = r2>>6; int li = r2&63; lane = li>>1; j = li&1;
        k = s*128 + kc*8 + (lane&3) + 4*j; n = nt*8 + (lane>>2);
        v = Wf2[k*256 + n];
    } else {
        int q = e-OFF_WO; kc = q>>11; int r2 = q&2047; nt = r2>>6; int li = r2&63; lane = li>>1; j = li&1;
        k = kc*8 + (lane&3) + 4*j; n = nt*8 + (lane>>2);
        v = Wo[k*256 + n];
    }
    u32 u; asm("cvt.rna.tf32.f32 %0, %1;" : "=r"(u) : "f"(v));
    g_tape[e] = __uint_as_float(u);
}

// --------- streamed warp-MMA GEMM, N=256 cols (32 global n-tiles) ---------
static __device__ __forceinline__ void gemm256(
    u32 a_sm, int astride, int kch, const float* tape, const float* nxt,
    float (*acc)[8][4], u32 wb, int &bufc, int t, int wrow, int ntb, int lane)
{
    const int nbuf = kch >> 1;          // 2 k-chunks (2048 fl each) per 16KB buffer
    for (int ib = 0; ib < nbuf; ib++){
        const float* src = (ib+1 < nbuf) ? tape + (size_t)(ib+1)*4096 : nxt;
        u32 dst = wb + (u32)(((bufc+1)&1)<<14);
        cp16u(dst + (u32)t*16, src + t*4);
        cp16u(dst + (u32)(t+512)*16, src + (t+512)*4);
        cp_commit(); cp_wait1(); __syncthreads();
        u32 cur = wb + (u32)((bufc&1)<<14);
        #pragma unroll
        for (int kk = 0; kk < 2; kk++){
            int kc = ib*2 + kk;
            int p0 = (kc*8 + (lane&3)) ^ ((lane>>2)<<2);
            int p1 = p0 ^ 4;
            u32 afr[2][4];
            #pragma unroll
            for (int mt = 0; mt < 2; mt++){
                u32 b0 = a_sm + (u32)((wrow + mt*16 + (lane>>2))*astride)*4;
                u32 b1a = b0 + (u32)(8*astride)*4;
                afr[mt][0] = cvtf(lds1(b0 + p0*4));
                afr[mt][2] = cvtf(lds1(b0 + p1*4));
                afr[mt][1] = cvtf(lds1(b1a + p0*4));
                afr[mt][3] = cvtf(lds1(b1a + p1*4));
            }
            #pragma unroll
            for (int nt = 0; nt < 8; nt++){
                u32 bb0, bb1;
                lds2u(cur + (u32)(kk*2048 + (ntb+nt)*64 + lane*2)*4, bb0, bb1);
                MMA(acc[0][nt], afr[0], bb0, bb1);
                MMA(acc[1][nt], afr[1], bb0, bb1);
            }
        }
        __syncthreads();
        bufc++;
    }
}

// --------- streamed warp-MMA GEMM, N=128 cols (16 global n-tiles) ---------
static __device__ __forceinline__ void gemm128(
    u32 a_sm, int astride, int kch, const float* tape, const float* nxt,
    float (*acc)[4][4], u32 wb, int &bufc, int t, int wrow, int ntb, int lane)
{
    const int nbuf = kch >> 2;          // 4 k-chunks (1024 fl each) per buffer
    for (int ib = 0; ib < nbuf; ib++){
        const float* src = (ib+1 < nbuf) ? tape + (size_t)(ib+1)*4096 : nxt;
        u32 dst = wb + (u32)(((bufc+1)&1)<<14);
        cp16u(dst + (u32)t*16, src + t*4);
        cp16u(dst + (u32)(t+512)*16, src + (t+512)*4);
        cp_commit(); cp_wait1(); __syncthreads();
        u32 cur = wb + (u32)((bufc&1)<<14);
        #pragma unroll
        for (int kk = 0; kk < 4; kk++){
            int kc = ib*4 + kk;
            int p0 = (kc*8 + (lane&3)) ^ ((lane>>2)<<2);
            int p1 = p0 ^ 4;
            u32 afr[2][4];
            #pragma unroll
            for (int mt = 0; mt < 2; mt++){
                u32 b0 = a_sm + (u32)((wrow + mt*16 + (lane>>2))*astride)*4;
                u32 b1a = b0 + (u32)(8*astride)*4;
                afr[mt][0] = cvtf(lds1(b0 + p0*4));
                afr[mt][2] = cvtf(lds1(b0 + p1*4));
                afr[mt][1] = cvtf(lds1(b1a + p0*4));
                afr[mt][3] = cvtf(lds1(b1a + p1*4));
            }
            #pragma unroll
            for (int nt = 0; nt < 4; nt++){
                u32 bb0, bb1;
                lds2u(cur + (u32)(kk*1024 + (ntb+nt)*64 + lane*2)*4, bb0, bb1);
                MMA(acc[0][nt], afr[0], bb0, bb1);
                MMA(acc[1][nt], afr[1], bb0, bb1);
            }
        }
        __syncthreads();
        bufc++;
    }
}

// Variadic: bodies may contain top-level commas.
#define EPI256(...) \
    _Pragma("unroll") for (int mt = 0; mt < 2; mt++) \
    _Pragma("unroll") for (int hi = 0; hi < 2; hi++) \
    _Pragma("unroll") for (int nt = 0; nt < 8; nt++) { \
        int row = wrow2 + mt*16 + hi*8 + rl; \
        int col = wcol2 + nt*8 + cl; \
        float c0v = acc2[mt][nt][hi*2+0]; \
        float c1v = acc2[mt][nt][hi*2+1]; \
        __VA_ARGS__; \
    }

__global__ void __launch_bounds__(NTHR, 1)
fractal_mma(const float* __restrict__ x, const float* __restrict__ z,
            const float* __restrict__ tbl,
            const float* __restrict__ b1, const float* __restrict__ b2,
            const float* __restrict__ bf1, const float* __restrict__ bf2,
            const float* __restrict__ bo,
            const int* __restrict__ resolutions, const float* __restrict__ freqs,
            float* __restrict__ out)
{
    extern __shared__ char smc[];
    const u32 smb = s2u(smc);
    const u32 wb  = smb + WB_OFF;
    const int t = threadIdx.x, w = t>>5, lane = t&31;
    const int r0 = blockIdx.x * MROWS;
    const int rl = lane>>2, xr = rl<<2, cl = 2*(lane&3);
    const int wrow2 = (w&3)*32, ntb2 = (w>>2)*8, wcol2 = (w>>2)*64;
    const int wrow1 = (w&3)*32, ntb1 = (w>>2)*4, wcol1 = (w>>2)*32;

    // ---------- feature stage -> feats (H region, stride FSTR, swizzled) ----------
    {
        int row = t >> 2, sub = t & 3, gr = r0 + row;
        float xn = fminf(fmaxf(x[gr], 0.0f), 1.0f);
        int fxr = (row & 7) << 2;
        #define FW(c, v) sts1(smb + H_OFF + (u32)(row*FSTR + ((c) ^ fxr))*4, (v))
        if (sub == 0) FW(0, xn);
        float aarg = 6.2831855f * xn;
        #pragma unroll
        for (int q = 0; q < 8; q++){
            int fi = sub*8 + q;
            double s, c; sincos((double)(aarg * freqs[fi]), &s, &c);
            FW(1+fi, (float)s); FW(33+fi, (float)c);
        }
        #pragma unroll
        for (int lq = 0; lq < 2; lq++){
            int lv = sub*2 + lq;
            int R = resolutions[lv];
            float tf = xn * (float)(R-1);
            int i0 = (int)floorf(tf), i1 = min(i0+1, R-1);
            float wt = tf - (float)i0;
            unsigned lt = (unsigned)(lv * 19349663);
            int h0 = (int)((((unsigned)i0*73856093u)^lt)&16383u);
            int h1 = (int)((((unsigned)i1*73856093u)^lt)&16383u);
            const float* e0 = tbl + ((size_t)lv*16384 + h0)*8;
            const float* e1 = tbl + ((size_t)lv*16384 + h1)*8;
            #pragma unroll
            for (int e = 0; e < 8; e++)
                FW(65 + lv*8 + e, e0[e]*(1.0f-wt) + e1[e]*wt);
        }
        #pragma unroll
        for (int q = 0; q < 8; q++)
            FW(129 + sub*8 + q, z[(size_t)gr*32 + sub*8 + q]);
        for (int c = 161 + sub; c < 176; c += 4)
            FW(c, 0.0f);
        #undef FW
    }
    __syncthreads();

    float acc2[2][8][4];
    int bufc = 0;

    // prime buffer 0 with W1 tape
    {
        const float* src = g_tape + OFF_W1;
        cp16u(wb + (u32)t*16, src + t*4);
        cp16u(wb + (u32)(t+512)*16, src + (t+512)*4);
        cp_commit();
    }

    // ---------------- GEMM0: feats @ W1 (K=176) -> gelu -> h ----------------
    #pragma unroll
    for (int i = 0; i < 2; i++) for (int j2 = 0; j2 < 8; j2++) for (int k2 = 0; k2 < 4; k2++)
        acc2[i][j2][k2] = 0.0f;
    gemm256(smb + H_OFF, FSTR, 22, g_tape + OFF_W1, g_tape + OFF_W2,
            acc2, wb, bufc, t, wrow2, ntb2, lane);
    EPI256(
        float v0 = gelu_e(c0v + __ldg(&b1[col]));
        float v1 = gelu_e(c1v + __ldg(&b1[col+1]));
        sts2(smb + H_OFF + (u32)(row*HSTR + (col ^ xr))*4, v0, v1);
    );

    // ---------------- h = gelu(h1 @ W2 + b2) ----------------
    #pragma unroll
    for (int i = 0; i < 2; i++) for (int j2 = 0; j2 < 8; j2++) for (int k2 = 0; k2 < 4; k2++)
        acc2[i][j2][k2] = 0.0f;
    gemm256(smb + H_OFF, HSTR, 32, g_tape + OFF_W2, g_tape + OFF_WF1,
            acc2, wb, bufc, t, wrow2, ntb2, lane);
    EPI256(
        float v0 = gelu_e(c0v + __ldg(&b2[col]));
        float v1 = gelu_e(c1v + __ldg(&b2[col+1]));
        sts2(smb + H_OFF + (u32)(row*HSTR + (col ^ xr))*4, v0, v1);
    );

    // ---------------- 48-step scan ----------------
    #pragma unroll 1
    for (int step = 0; step < Tn; step++){
        #pragma unroll 1
        for (int s = 0; s < 4; s++){
            const float* wf1s = g_tape + OFF_WF1 + (size_t)s*32768;
            const float* wf2s = g_tape + OFF_WF2 + (size_t)s*32768;
            // G1 slice: g = gelu(h @ Wf1[:, s*128:+128] + bf1-slice)
            float acc1[2][4][4];
            #pragma unroll
            for (int i = 0; i < 2; i++) for (int j2 = 0; j2 < 4; j2++) for (int k2 = 0; k2 < 4; k2++)
                acc1[i][j2][k2] = 0.0f;
            gemm128(smb + H_OFF, HSTR, 32, wf1s, wf2s,
                    acc1, wb, bufc, t, wrow1, ntb1, lane);
            #pragma unroll
            for (int mt = 0; mt < 2; mt++)
            #pragma unroll
            for (int hi = 0; hi < 2; hi++)
            #pragma unroll
            for (int nt = 0; nt < 4; nt++){
                int row = wrow1 + mt*16 + hi*8 + rl;
                int col = wcol1 + nt*8 + cl;
                float v0 = gelu_e(acc1[mt][nt][hi*2+0] + __ldg(&bf1[s*128+col]));
                float v1 = gelu_e(acc1[mt][nt][hi*2+1] + __ldg(&bf1[s*128+col+1]));
                sts2(smb + G_OFF + (u32)(row*GSTR + (col ^ xr))*4, v0, v1);
            }
            // G2 partial: acc2 += g @ Wf2[s*128:+128, :]
            if (s == 0){
                #pragma unroll
                for (int i = 0; i < 2; i++) for (int j2 = 0; j2 < 8; j2++) for (int k2 = 0; k2 < 4; k2++)
                    acc2[i][j2][k2] = 0.0f;
            }
            const float* nxt2 = (s < 3) ? g_tape + OFF_WF1 + (size_t)(s+1)*32768
                               : (step < Tn-1 ? g_tape + OFF_WF1 : g_tape + OFF_WO);
            gemm256(smb + G_OFF, GSTR, 16, wf2s, nxt2,
                    acc2, wb, bufc, t, wrow2, ntb2, lane);
        }
        // epi: u = tanh(acc2 + bf2); h = 0.5h + 0.5u
        EPI256(
            u32 ha = smb + H_OFF + (u32)(row*HSTR + (col ^ xr))*4;
            float o0, o1; lds2f(ha, o0, o1);
            float u0 = tanh_a(c0v + __ldg(&bf2[col]));
            float u1 = tanh_a(c1v + __ldg(&bf2[col+1]));
            sts2(ha, 0.5f*o0 + 0.5f*u0, 0.5f*o1 + 0.5f*u1);
        );
    }

    // ---------------- final: out = h @ Wo + bo ----------------
    #pragma unroll
    for (int i = 0; i < 2; i++) for (int j2 = 0; j2 < 8; j2++) for (int k2 = 0; k2 < 4; k2++)
        acc2[i][j2][k2] = 0.0f;
    gemm256(smb + H_OFF, HSTR, 32, g_tape + OFF_WO, g_tape + OFF_WO,
            acc2, wb, bufc, t, wrow2, ntb2, lane);
    EPI256(
        float2 vv = make_float2(c0v + __ldg(&bo[col]), c1v + __ldg(&bo[col+1]));
        *(float2*)&out[(size_t)(r0+row)*256 + col] = vv;
    );
    cp_wait0();
}

extern "C" void kernel_launch(void* const* d_in, const int* in_sizes, int n_in,
                              void* d_out, int out_size)
{
    (void)out_size;
    const float *x=0,*z=0,*tbl=0,*W1=0,*b1=0,*W2=0,*b2=0,*Wf1=0,*bf1=0,*Wf2=0,*bf2=0,*Wo=0,*bo=0,*frq=0;
    const int* res=0;
    int c65536=0, c131072=0, c256=0;
    for (int i = 0; i < n_in; i++){
        const void* p = d_in[i];
        switch (in_sizes[i]){
            case 16384:   x   = (const float*)p; break;
            case 524288:  z   = (const float*)p; break;
            case 1048576: tbl = (const float*)p; break;
            case 41216:   W1  = (const float*)p; break;
            case 512:     bf1 = (const float*)p; break;
            case 8:       res = (const int*)p;   break;
            case 32:      frq = (const float*)p; break;
            case 65536:   if (c65536++  == 0) W2  = (const float*)p; else Wo  = (const float*)p; break;
            case 131072:  if (c131072++ == 0) Wf1 = (const float*)p; else Wf2 = (const float*)p; break;
            case 256:
                switch (c256++){
                    case 0: b1 = (const float*)p; break;
                    case 1: b2 = (const float*)p; break;
                    case 2: bf2 = (const float*)p; break;
                    default: bo = (const float*)p; break;
                }
                break;
            default: break;
        }
    }
    float* out = (float*)d_out;

    prep_tape<<<(NTAPE + 255)/256, 256>>>(W1, W2, Wf1, Wf2, Wo);

    cudaFuncSetAttribute(fractal_mma, cudaFuncAttributeMaxDynamicSharedMemorySize, SMEM_BYTES);
    fractal_mma<<<Bn/MROWS, NTHR, SMEM_BYTES>>>(x, z, tbl, b1, b2, bf1, bf2, bo, res, frq, out);
}

// round 11
// speedup vs baseline: 5.3755x; 1.6633x over previous
#include <cuda_runtime.h>
#include <cuda_fp16.h>
#include <math.h>

// ---------------------------------------------------------------------------
// FractalDecoderV6 — fp16 m16n8k16 mma.sync (fp32 accumulate).
// 128 rows/CTA, 128 CTAs, 512 threads. Pre-packed fp16 B-fragment tape,
// lds.64 A fragments via k-permutation, single-barrier 32KB weight buffers.
// R11: exact tape segment sizes (fixes OOB read of W2 in prep_tape).
// ---------------------------------------------------------------------------

typedef unsigned int u32;

#define Bn    16384
#define Tn    48
#define MROWS 128
#define NTHR  512

#define H_OFF    0        // h / feats: 128 x 256 halves (64KB), swizzled
#define G_OFF    65536    // g slice:   128 x 128 halves (32KB)
#define WB_OFF   98304    // 2 x 32KB weight buffers
#define BIAS_OFF 163840   // 6KB fp32 biases
#define SMEM_BYTES 169984

#define B1_B  0
#define B2_B  1024
#define BF1_B 2048
#define BF2_B 4096
#define BO_B  5120

// tape offsets (halves) — exact sizes
#define T_W1   0          // 12 kc (K=192)  -> 49152
#define T_W2   49152      // 16 kc (K=256)  -> 65536
#define T_SCAN 114688     // 4 x [G1 32768 | G2 32768] = 262144
#define T_WO   376832     // 16 kc (K=256)  -> 65536
#define NTAPE  442368
__device__ __align__(256) __half g_tape[NTAPE];

static __device__ __forceinline__ u32 s2u(const void* p){
    u32 a; asm("{ .reg .u64 t; cvta.to.shared.u64 t, %1; cvt.u32.u64 %0, t; }":"=r"(a):"l"(p)); return a;
}
static __device__ __forceinline__ void cp16u(u32 dst, const void* src){
    asm volatile("cp.async.cg.shared.global [%0], [%1], 16;" :: "r"(dst), "l"(src));
}
static __device__ __forceinline__ void cp_commit(){ asm volatile("cp.async.commit_group;"); }
static __device__ __forceinline__ void cp_wait0(){ asm volatile("cp.async.wait_group 0;"); }
static __device__ __forceinline__ void lds2u(u32 a, u32 &x, u32 &y){
    asm volatile("ld.shared.v2.b32 {%0,%1}, [%2];" : "=r"(x), "=r"(y) : "r"(a));
}
static __device__ __forceinline__ u32 lds32u(u32 a){
    u32 v; asm volatile("ld.shared.b32 %0, [%1];" : "=r"(v) : "r"(a)); return v;
}
static __device__ __forceinline__ void sts32u(u32 a, u32 v){
    asm volatile("st.shared.b32 [%0], %1;" :: "r"(a), "r"(v) : "memory");
}
static __device__ __forceinline__ void sts16(u32 a, __half h){
    unsigned short b = __half_as_ushort(h);
    asm volatile("st.shared.b16 [%0], %1;" :: "r"(a), "h"(b) : "memory");
}
static __device__ __forceinline__ void stsf(u32 a, float v){
    asm volatile("st.shared.f32 [%0], %1;" :: "r"(a), "f"(v) : "memory");
}
static __device__ __forceinline__ float2 ldsf2(u32 a){
    float2 v; asm volatile("ld.shared.v2.f32 {%0,%1}, [%2];" : "=f"(v.x), "=f"(v.y) : "r"(a)); return v;
}

#define MMA16(d, A0,A1,A2,A3, B0,B1) \
    asm volatile("mma.sync.aligned.m16n8k16.row.col.f32.f16.f16.f32 " \
        "{%0,%1,%2,%3},{%4,%5,%6,%7},{%8,%9},{%0,%1,%2,%3};" \
        : "+f"((d)[0]),"+f"((d)[1]),"+f"((d)[2]),"+f"((d)[3]) \
        : "r"(A0),"r"(A1),"r"(A2),"r"(A3),"r"(B0),"r"(B1))

static __device__ __forceinline__ float gelu_e(float v){
    return 0.5f*v*(1.0f+erff(v*0.70710678118654752f));
}
static __device__ __forceinline__ float tanh_a(float x){
    float a = fabsf(x), em = expm1f(-2.0f*a);
    return copysignf(-em/(2.0f+em), x);
}
static __device__ __forceinline__ u32 haddr(u32 smb, int row, int col){
    return smb + H_OFF + (u32)(((row<<8) + (col ^ ((row&7)<<4)))<<1);
}
static __device__ __forceinline__ u32 gaddr(u32 smb, int row, int col){
    return smb + G_OFF + (u32)(((row<<7) + (col ^ ((row&7)<<4)))<<1);
}

// --------- prep: fp16-round weights + pack into B-fragment tape ---------
// B frag unit per (kc, nt, lane): 4 halves m=0..3 -> W[kc*16 + 4*(lane&3) + m, n]
__global__ void prep_tape(const float* __restrict__ W1, const float* __restrict__ W2,
                          const float* __restrict__ Wf1, const float* __restrict__ Wf2,
                          const float* __restrict__ Wo){
    int e = blockIdx.x*blockDim.x + threadIdx.x;
    if (e >= NTAPE) return;
    float v;
    if (e < T_W2){                       // 12 kc, K padded 161->192
        int q = e, kc = q>>12, r = q&4095, nt = r>>7, lane = (r>>2)&31, m = r&3;
        int k = kc*16 + 4*(lane&3) + m, n = nt*8 + (lane>>2);
        v = (k < 161) ? W1[k*256 + n] : 0.0f;
    } else if (e < T_SCAN){              // 16 kc, K=256
        int q = e-T_W2, kc = q>>12, r = q&4095, nt = r>>7, lane = (r>>2)&31, m = r&3;
        int k = kc*16 + 4*(lane&3) + m, n = nt*8 + (lane>>2);
        v = W2[k*256 + n];
    } else if (e < T_WO){
        int q = e-T_SCAN, s = q>>16, q2 = q&65535;
        if (q2 < 32768){  // G1: Wf1 slice s, N=128 (16 nt), K=256
            int kc = q2>>11, r = q2&2047, nt = r>>7, lane = (r>>2)&31, m = r&3;
            int k = kc*16 + 4*(lane&3) + m, n = s*128 + nt*8 + (lane>>2);
            v = Wf1[k*512 + n];
        } else {          // G2: Wf2 rows s*128..+128, N=256 (32 nt)
            int q3 = q2-32768, kc = q3>>12, r = q3&4095, nt = r>>7, lane = (r>>2)&31, m = r&3;
            int k = s*128 + kc*16 + 4*(lane&3) + m, n = nt*8 + (lane>>2);
            v = Wf2[k*256 + n];
        }
    } else {                             // Wo: 16 kc, K=256
        int q = e-T_WO, kc = q>>12, r = q&4095, nt = r>>7, lane = (r>>2)&31, m = r&3;
        int k = kc*16 + 4*(lane&3) + m, n = nt*8 + (lane>>2);
        v = Wo[k*256 + n];
    }
    g_tape[e] = __float2half_rn(v);
}

// --------- streamed warp-MMA GEMM (single barrier per 32KB buffer) ---------
template<int NTW>
static __device__ __forceinline__ void gemmT(
    u32 a_sm, int astride, int nbuf, const __half* seg, const __half* nxt,
    float (*acc)[4], u32 wb, int &pc, int t, int wrow, int ntb, int lane)
{
    const int KCPB = (NTW==8) ? 4 : 8;
    const int NTG  = (NTW==8) ? 32 : 16;
    const int rl = lane>>2, li = lane&3;
    for (int ib = 0; ib < nbuf; ib++){
        cp_wait0(); __syncthreads();
        const char* src = (const char*)((ib+1 < nbuf) ? (seg + (size_t)(ib+1)*16384) : nxt);
        u32 dst = wb + (u32)(((pc+1)&1)<<15);
        #pragma unroll
        for (int i = 0; i < 4; i++)
            cp16u(dst + (u32)(t*16 + i*8192), src + t*16 + i*8192);
        cp_commit();
        u32 cur = wb + (u32)((pc&1)<<15);
        #pragma unroll
        for (int kk = 0; kk < KCPB; kk++){
            int kcg = ib*KCPB + kk;
            u32 a0[2], a1[2], a2[2], a3[2];
            #pragma unroll
            for (int mt = 0; mt < 2; mt++){
                int r1 = wrow + mt*16 + rl;
                int c  = (kcg*16 + 4*li) ^ (rl<<4);      // (r1&7)==rl
                u32 base = a_sm + (u32)((r1*astride + c)<<1);
                lds2u(base, a0[mt], a2[mt]);
                lds2u(base + (u32)(astride<<4), a1[mt], a3[mt]);   // +8 rows
            }
            #pragma unroll
            for (int nt = 0; nt < NTW; nt++){
                u32 b0, b1v;
                lds2u(cur + (u32)(((kk*NTG + ntb + nt)*32 + lane)<<3), b0, b1v);
                MMA16(acc[0*NTW+nt], a0[0], a1[0], a2[0], a3[0], b0, b1v);
                MMA16(acc[1*NTW+nt], a0[1], a1[1], a2[1], a3[1], b0, b1v);
            }
        }
        pc++;
    }
}

#define EPI8(...) \
    _Pragma("unroll") for (int mt = 0; mt < 2; mt++) \
    _Pragma("unroll") for (int hi = 0; hi < 2; hi++) \
    _Pragma("unroll") for (int nt = 0; nt < 8; nt++) { \
        int row = wrow2 + mt*16 + hi*8 + rl; \
        int col = wcol2 + nt*8 + cl; \
        float c0v = acc2[mt*8+nt][hi*2+0]; \
        float c1v = acc2[mt*8+nt][hi*2+1]; \
        __VA_ARGS__; \
    }

__global__ void __launch_bounds__(NTHR, 1)
fractal_h16(const float* __restrict__ x, const float* __restrict__ z,
            const float* __restrict__ tbl,
            const float* __restrict__ b1, const float* __restrict__ b2,
            const float* __restrict__ bf1, const float* __restrict__ bf2,
            const float* __restrict__ bo,
            const int* __restrict__ resolutions, const float* __restrict__ freqs,
            float* __restrict__ out)
{
    extern __shared__ char smc[];
    const u32 smb = s2u(smc);
    const u32 wb  = smb + WB_OFF;
    const int t = threadIdx.x, w = t>>5, lane = t&31;
    const int r0 = blockIdx.x * MROWS;
    const int rl = lane>>2, cl = 2*(lane&3);
    const int wrow2 = (w&3)*32, ntb2 = (w>>2)*8, wcol2 = (w>>2)*64;
    const int wrow1 = (w&3)*32, ntb1 = (w>>2)*4, wcol1 = (w>>2)*32;

    // biases -> SMEM
    if (t < 256){
        stsf(smb+BIAS_OFF+B1_B + t*4, b1[t]);
        stsf(smb+BIAS_OFF+B2_B + t*4, b2[t]);
        stsf(smb+BIAS_OFF+BF2_B + t*4, bf2[t]);
        stsf(smb+BIAS_OFF+BO_B + t*4, bo[t]);
    }
    stsf(smb+BIAS_OFF+BF1_B + t*4, bf1[t]);

    // prime: W1 buffer 0
    {
        const char* src = (const char*)(g_tape + T_W1);
        #pragma unroll
        for (int i = 0; i < 4; i++)
            cp16u(wb + (u32)(t*16 + i*8192), src + t*16 + i*8192);
        cp_commit();
    }
    int pc = 0;

    // ---------- feature stage -> H region (fp16, K padded to 192) ----------
    {
        int row = t >> 2, sub = t & 3, gr = r0 + row;
        float xn = fminf(fmaxf(x[gr], 0.0f), 1.0f);
        #define FWH(c, v) sts16(smb + H_OFF + (u32)((((row)<<8) + ((c) ^ ((row&7)<<4)))<<1), __float2half_rn(v))
        if (sub == 0) FWH(0, xn);
        float aarg = 6.2831855f * xn;
        #pragma unroll
        for (int q = 0; q < 8; q++){
            int fi = sub*8 + q;
            double s, c; sincos((double)(aarg * freqs[fi]), &s, &c);
            FWH(1+fi, (float)s); FWH(33+fi, (float)c);
        }
        #pragma unroll
        for (int lq = 0; lq < 2; lq++){
            int lv = sub*2 + lq;
            int R = resolutions[lv];
            float tf = xn * (float)(R-1);
            int i0 = (int)floorf(tf), i1 = min(i0+1, R-1);
            float wt = tf - (float)i0;
            unsigned lt = (unsigned)(lv * 19349663);
            int h0 = (int)((((unsigned)i0*73856093u)^lt)&16383u);
            int h1 = (int)((((unsigned)i1*73856093u)^lt)&16383u);
            const float* e0 = tbl + ((size_t)lv*16384 + h0)*8;
            const float* e1 = tbl + ((size_t)lv*16384 + h1)*8;
            #pragma unroll
            for (int e = 0; e < 8; e++)
                FWH(65 + lv*8 + e, e0[e]*(1.0f-wt) + e1[e]*wt);
        }
        #pragma unroll
        for (int q = 0; q < 8; q++)
            FWH(129 + sub*8 + q, z[(size_t)gr*32 + sub*8 + q]);
        for (int c = 161 + sub; c < 192; c += 4)
            FWH(c, 0.0f);
        #undef FWH
    }

    float acc2[16][4];
    #pragma unroll
    for (int i = 0; i < 16; i++) for (int j = 0; j < 4; j++) acc2[i][j] = 0.0f;

    // ---------------- GEMM0: feats @ W1 (K=192, 3 buffers) ----------------
    gemmT<8>(smb+H_OFF, 256, 3, g_tape+T_W1, g_tape+T_W2, acc2, wb, pc, t, wrow2, ntb2, lane);
    __syncthreads();   // H overwrite vs lagging readers
    EPI8(
        float2 bb = ldsf2(smb+BIAS_OFF+B1_B + col*4);
        __half2 hh = __floats2half2_rn(gelu_e(c0v + bb.x), gelu_e(c1v + bb.y));
        sts32u(haddr(smb, row, col), *(u32*)&hh);
    );

    // ---------------- h = gelu(h1 @ W2 + b2) ----------------
    #pragma unroll
    for (int i = 0; i < 16; i++) for (int j = 0; j < 4; j++) acc2[i][j] = 0.0f;
    gemmT<8>(smb+H_OFF, 256, 4, g_tape+T_W2, g_tape+T_SCAN, acc2, wb, pc, t, wrow2, ntb2, lane);
    __syncthreads();
    EPI8(
        float2 bb = ldsf2(smb+BIAS_OFF+B2_B + col*4);
        __half2 hh = __floats2half2_rn(gelu_e(c0v + bb.x), gelu_e(c1v + bb.y));
        sts32u(haddr(smb, row, col), *(u32*)&hh);
    );

    // ---------------- 48-step scan ----------------
    #pragma unroll 1
    for (int step = 0; step < Tn; step++){
        #pragma unroll 1
        for (int s = 0; s < 4; s++){
            const __half* g1s = g_tape + T_SCAN + (size_t)s*65536;
            const __half* g2s = g1s + 32768;
            float acc1[8][4];
            #pragma unroll
            for (int i = 0; i < 8; i++) for (int j = 0; j < 4; j++) acc1[i][j] = 0.0f;
            gemmT<4>(smb+H_OFF, 256, 2, g1s, g2s, acc1, wb, pc, t, wrow1, ntb1, lane);
            // G1 epi: g = gelu(. + bf1 slice) -> G region (fp16)
            #pragma unroll
            for (int mt = 0; mt < 2; mt++)
            #pragma unroll
            for (int hi = 0; hi < 2; hi++)
            #pragma unroll
            for (int nt = 0; nt < 4; nt++){
                int row = wrow1 + mt*16 + hi*8 + rl;
                int col = wcol1 + nt*8 + cl;
                float2 bb = ldsf2(smb+BIAS_OFF+BF1_B + (s*128+col)*4);
                __half2 hh = __floats2half2_rn(gelu_e(acc1[mt*4+nt][hi*2+0] + bb.x),
                                               gelu_e(acc1[mt*4+nt][hi*2+1] + bb.y));
                sts32u(gaddr(smb, row, col), *(u32*)&hh);
            }
            if (s == 0){
                #pragma unroll
                for (int i = 0; i < 16; i++) for (int j = 0; j < 4; j++) acc2[i][j] = 0.0f;
            }
            const __half* nxt = (s < 3) ? (g_tape + T_SCAN + (size_t)(s+1)*65536)
                               : (step < Tn-1 ? g_tape + T_SCAN : g_tape + T_WO);
            gemmT<8>(smb+G_OFF, 128, 2, g2s, nxt, acc2, wb, pc, t, wrow2, ntb2, lane);
        }
        // blend epi: u = tanh(. + bf2); h = 0.5h + 0.5u
        EPI8(
            float2 bb = ldsf2(smb+BIAS_OFF+BF2_B + col*4);
            float u0 = tanh_a(c0v + bb.x);
            float u1 = tanh_a(c1v + bb.y);
            u32 ha = haddr(smb, row, col);
            u32 ob = lds32u(ha);
            float2 of = __half22float2(*(__half2*)&ob);
            __half2 hh = __floats2half2_rn(0.5f*of.x + 0.5f*u0, 0.5f*of.y + 0.5f*u1);
            sts32u(ha, *(u32*)&hh);
        );
    }

    // ---------------- final: out = h @ Wo + bo ----------------
    #pragma unroll
    for (int i = 0; i < 16; i++) for (int j = 0; j < 4; j++) acc2[i][j] = 0.0f;
    gemmT<8>(smb+H_OFF, 256, 4, g_tape+T_WO, g_tape+T_W1, acc2, wb, pc, t, wrow2, ntb2, lane);
    EPI8(
        float2 bb = ldsf2(smb+BIAS_OFF+BO_B + col*4);
        float2 vv = make_float2(c0v + bb.x, c1v + bb.y);
        *(float2*)&out[(size_t)(r0+row)*256 + col] = vv;
    );
    cp_wait0();
}

extern "C" void kernel_launch(void* const* d_in, const int* in_sizes, int n_in,
                              void* d_out, int out_size)
{
    (void)out_size;
    const float *x=0,*z=0,*tbl=0,*W1=0,*b1=0,*W2=0,*b2=0,*Wf1=0,*bf1=0,*Wf2=0,*bf2=0,*Wo=0,*bo=0,*frq=0;
    const int* res=0;
    int c65536=0, c131072=0, c256=0;
    for (int i = 0; i < n_in; i++){
        const void* p = d_in[i];
        switch (in_sizes[i]){
            case 16384:   x   = (const float*)p; break;
            case 524288:  z   = (const float*)p; break;
            case 1048576: tbl = (const float*)p; break;
            case 41216:   W1  = (const float*)p; break;
            case 512:     bf1 = (const float*)p; break;
            case 8:       res = (const int*)p;   break;
            case 32:      frq = (const float*)p; break;
            case 65536:   if (c65536++  == 0) W2  = (const float*)p; else Wo  = (const float*)p; break;
            case 131072:  if (c131072++ == 0) Wf1 = (const float*)p; else Wf2 = (const float*)p; break;
            case 256:
                switch (c256++){
                    case 0: b1 = (const float*)p; break;
                    case 1: b2 = (const float*)p; break;
                    case 2: bf2 = (const float*)p; break;
                    default: bo = (const float*)p; break;
                }
                break;
            default: break;
        }
    }
    float* out = (float*)d_out;

    prep_tape<<<(NTAPE + 255)/256, 256>>>(W1, W2, Wf1, Wf2, Wo);

    cudaFuncSetAttribute(fractal_h16, cudaFuncAttributeMaxDynamicSharedMemorySize, SMEM_BYTES);
    fractal_h16<<<Bn/MROWS, NTHR, SMEM_BYTES>>>(x, z, tbl, b1, b2, bf1, bf2, bo, res, frq, out);
}